// round 5
// baseline (speedup 1.0000x reference)
#include <cuda_runtime.h>
#include <cuda_bf16.h>
#include <math.h>
#include <stdint.h>

// Problem-fixed shapes
#define B_ 1024
#define T_ 128
#define MX_ (B_ * T_)   // 131072 rows for input-projection GEMMs

// Inter-layer activation buffers + input-projection scratch (allocation-free).
__device__ float g_buf1[MX_ * 128];      // layer1 out [B,T,128]
__device__ float g_buf2[MX_ * 64];       // layer2 out [B,T,64]
__device__ float g_buf3[B_ * 32];        // layer3 out [B,32]
__device__ float g_xzf[MX_ * 256];       // fwd input projection, [row][u][gate]
__device__ float g_xzb[MX_ * 256];       // bwd input projection

__device__ __forceinline__ float sigf(float x) {
    return __fdividef(1.0f, 1.0f + __expf(-x));
}
__device__ __forceinline__ float tanhf_fast(float x) {
    return __fdividef(2.0f, 1.0f + __expf(-2.0f * x)) - 1.0f;
}

// ---------------------------------------------------------------------------
// Split-bf16 GEMM on tensor cores: C[MX, NGL] = X[MX, K] @ W[K, NGL] in ~fp32
// accuracy via 3-term bf16 split (hi*hi + hi*lo + lo*hi). mma.sync m16n8k16.
// Epilogue writes PERMUTED layout out[row][u][gate] (u = n % U, gate = n / U)
// so the recurrent kernel reads one float4 per unit.
// Block: 128 thr (4 warps), tile M=64 x N=64. grid = (MX/64, NGL/64, 2 dirs).
// ---------------------------------------------------------------------------
__device__ __forceinline__ uint32_t pack_split(float v0, float v1, uint32_t& lo) {
    __nv_bfloat16 h0 = __float2bfloat16(v0);
    __nv_bfloat16 h1 = __float2bfloat16(v1);
    float r0 = v0 - __bfloat162float(h0);
    float r1 = v1 - __bfloat162float(h1);
    __nv_bfloat16 l0 = __float2bfloat16(r0);
    __nv_bfloat16 l1 = __float2bfloat16(r1);
    lo = ((uint32_t)__bfloat16_as_ushort(l1) << 16) | (uint32_t)__bfloat16_as_ushort(l0);
    return ((uint32_t)__bfloat16_as_ushort(h1) << 16) | (uint32_t)__bfloat16_as_ushort(h0);
}

__device__ __forceinline__ void mma_bf16(float* c, const uint32_t* a, uint32_t b0, uint32_t b1) {
    asm volatile(
        "mma.sync.aligned.m16n8k16.row.col.f32.bf16.bf16.f32 "
        "{%0,%1,%2,%3}, {%4,%5,%6,%7}, {%8,%9}, {%0,%1,%2,%3};\n"
        : "+f"(c[0]), "+f"(c[1]), "+f"(c[2]), "+f"(c[3])
        : "r"(a[0]), "r"(a[1]), "r"(a[2]), "r"(a[3]), "r"(b0), "r"(b1));
}

template <int K, int KP, int NGL>
__global__ void __launch_bounds__(128) inproj_gemm(
    const float* __restrict__ X,     // [MX, K]
    const float* __restrict__ Wf,    // [K, NGL] gate-major columns
    const float* __restrict__ Wb,
    float* __restrict__ outf,        // [MX, NGL] permuted (u,gate)
    float* __restrict__ outb)
{
    constexpr int U = NGL / 4;
    constexpr int AS_STRIDE = KP + 4;     // bank-spread fp32 A tile
    constexpr int NPAIR = KP / 2;
    constexpr int WS = 65;                // padded u32 stride for W pairs

    extern __shared__ float smraw[];
    float* As = smraw;                                   // 64 * AS_STRIDE
    uint32_t* Whi = (uint32_t*)(As + 64 * AS_STRIDE);    // NPAIR * WS
    uint32_t* Wlo = Whi + NPAIR * WS;

    const float* W = blockIdx.z ? Wb : Wf;
    float* out = blockIdx.z ? outb : outf;
    const int m0 = blockIdx.x * 64;
    const int n0 = blockIdx.y * 64;
    const int tid = threadIdx.x;

    // Stage A tile fp32, zero-padding K..KP
    for (int i = tid; i < 64 * KP; i += 128) {
        int r = i / KP, c = i % KP;
        As[r * AS_STRIDE + c] = (c < K) ? X[(size_t)(m0 + r) * K + c] : 0.0f;
    }
    // Stage W tile, split hi/lo bf16, packed (even-k low, odd-k high) = B-frag format
    for (int i = tid; i < NPAIR * 64; i += 128) {
        int mp = i / 64, n = i % 64;
        int k0 = 2 * mp, k1 = 2 * mp + 1;
        float w0 = (k0 < K) ? W[(size_t)k0 * NGL + n0 + n] : 0.0f;
        float w1 = (k1 < K) ? W[(size_t)k1 * NGL + n0 + n] : 0.0f;
        uint32_t lo;
        uint32_t hi = pack_split(w0, w1, lo);
        Whi[mp * WS + n] = hi;
        Wlo[mp * WS + n] = lo;
    }
    __syncthreads();

    const int wid = tid >> 5, lane = tid & 31;
    const int g = lane >> 2, i4 = lane & 3;
    const int mrow = wid * 16;

    float acc[8][4];
#pragma unroll
    for (int nt = 0; nt < 8; ++nt)
#pragma unroll
        for (int q = 0; q < 4; ++q) acc[nt][q] = 0.0f;

#pragma unroll
    for (int kc = 0; kc < KP / 16; ++kc) {
        uint32_t ahi[4], alo[4];
#pragma unroll
        for (int fi = 0; fi < 4; ++fi) {
            int r = mrow + g + (fi & 1) * 8;
            int kk = kc * 16 + 2 * i4 + (fi >> 1) * 8;
            float v0 = As[r * AS_STRIDE + kk];
            float v1 = As[r * AS_STRIDE + kk + 1];
            ahi[fi] = pack_split(v0, v1, alo[fi]);
        }
#pragma unroll
        for (int nt = 0; nt < 8; ++nt) {
            int nn = nt * 8 + g;
            uint32_t bh0 = Whi[(kc * 8 + i4) * WS + nn];
            uint32_t bh1 = Whi[(kc * 8 + 4 + i4) * WS + nn];
            uint32_t bl0 = Wlo[(kc * 8 + i4) * WS + nn];
            uint32_t bl1 = Wlo[(kc * 8 + 4 + i4) * WS + nn];
            mma_bf16(acc[nt], ahi, bh0, bh1);   // hi*hi
            mma_bf16(acc[nt], ahi, bl0, bl1);   // hi*lo
            mma_bf16(acc[nt], alo, bh0, bh1);   // lo*hi
        }
    }

    // Write out, permuted to [row][u][gate]
#pragma unroll
    for (int nt = 0; nt < 8; ++nt) {
#pragma unroll
        for (int q = 0; q < 4; ++q) {
            int n = n0 + nt * 8 + 2 * i4 + (q & 1);     // global gate-major col
            size_t r = (size_t)(m0 + mrow + g + (q >> 1) * 8);
            int uu = n % U, gg = n / U;
            out[r * NGL + uu * 4 + gg] = acc[nt][q];
        }
    }
}

// ---------------------------------------------------------------------------
// Recurrent kernel v2: broadcast-weight, row-lane layout.
// Block covers 8 batch rows; lane = (us, r): r = lane&7 (row), us = lane>>3.
// Warp w owns units { w*4*NU + k*4 + us : k<NU }. Weight LDS.128 per (u2,k) is
// 4 consecutive float4 across the warp (64B, 1 wavefront); h read as LDS.128
// of 4 consecutive h values (8 rows x 16B, conflict-free via UP=U+4 stride).
// xz precomputed & permuted: one float4 (i,f,g,o) per unit per step, with
// register prefetch of the next step. One __syncthreads per step.
// grid = (B/8, 2 dirs).
// ---------------------------------------------------------------------------
template <int U, int NU, bool SEQ>
__global__ void __launch_bounds__(32 * (U / (4 * NU))) lstm_rec2(
    const float* __restrict__ xzf, const float* __restrict__ xzb,  // [MX, 4U] permuted
    const float* __restrict__ Wrf, const float* __restrict__ bf,
    const float* __restrict__ Wrb, const float* __restrict__ bb,
    float* __restrict__ out)         // SEQ: [B, T, 2U]  else: [B, 2U]
{
    constexpr int G4 = 4 * U;
    constexpr int NW = U / (4 * NU);
    constexpr int NT = 32 * NW;
    constexpr int UP = U + 4;        // padded h stride (16B aligned, bank-spread)

    extern __shared__ float sm[];
    float* Wr_s = sm;                 // U * G4, gate-interleaved [u2][u][4]
    float* b_s  = Wr_s + U * G4;      // G4, [u][4]
    float* hs0  = b_s + G4;           // 8 * UP
    float* hs1  = hs0 + 8 * UP;       // 8 * UP

    const int dir = blockIdx.y;
    const float* Wr   = dir ? Wrb : Wrf;
    const float* bias = dir ? bb  : bf;
    const float* xz   = dir ? xzb : xzf;

    const int tid = threadIdx.x;

    for (int i = tid; i < U * G4; i += NT) {
        int u2 = i / G4, c = i % G4, u = c >> 2, gg = c & 3;
        Wr_s[i] = Wr[u2 * G4 + gg * U + u];
    }
    for (int i = tid; i < G4; i += NT) b_s[i] = bias[(i & 3) * U + (i >> 2)];
    for (int i = tid; i < 8 * UP; i += NT) { hs0[i] = 0.0f; hs1[i] = 0.0f; }

    const int w    = tid >> 5;
    const int lane = tid & 31;
    const int r    = lane & 7;
    const int us   = lane >> 3;
    const int b0   = blockIdx.x * 8;

    int uk[NU];
#pragma unroll
    for (int k = 0; k < NU; ++k) uk[k] = w * 4 * NU + k * 4 + us;

    const size_t rowbase = (size_t)(b0 + r) * T_;

    float cst[NU], hlast[NU];
    float4 cx[NU];
#pragma unroll
    for (int k = 0; k < NU; ++k) { cst[k] = 0.0f; hlast[k] = 0.0f; }

    {
        const int t0 = dir ? (T_ - 1) : 0;
#pragma unroll
        for (int k = 0; k < NU; ++k)
            cx[k] = *(const float4*)(xz + (rowbase + t0) * G4 + uk[k] * 4);
    }
    __syncthreads();

    float4 bvv[NU];
#pragma unroll
    for (int k = 0; k < NU; ++k) bvv[k] = ((const float4*)b_s)[uk[k]];

    const float4* __restrict__ wr4 = (const float4*)Wr_s;
    float* hs_c = hs0; float* hs_n = hs1;

    for (int s = 0; s < T_; ++s) {
        const int t  = dir ? (T_ - 1 - s) : s;
        const int sn = (s + 1 < T_) ? (s + 1) : s;
        const int tn = dir ? (T_ - 1 - sn) : sn;

        // Prefetch next step's xz (one float4 per unit).
        float4 pre[NU];
#pragma unroll
        for (int k = 0; k < NU; ++k)
            pre[k] = *(const float4*)(xz + (rowbase + tn) * G4 + uk[k] * 4);

        float4 a[NU];
#pragma unroll
        for (int k = 0; k < NU; ++k) {
            a[k].x = bvv[k].x + cx[k].x;
            a[k].y = bvv[k].y + cx[k].y;
            a[k].z = bvv[k].z + cx[k].z;
            a[k].w = bvv[k].w + cx[k].w;
        }

        // Recurrent projection: h @ Wr, broadcast weights.
#pragma unroll
        for (int u4 = 0; u4 < U / 4; ++u4) {
            float4 h4 = *(const float4*)(hs_c + r * UP + u4 * 4);
#pragma unroll
            for (int q = 0; q < 4; ++q) {
                float hv = (&h4.x)[q];
#pragma unroll
                for (int k = 0; k < NU; ++k) {
                    float4 wv = wr4[(u4 * 4 + q) * U + uk[k]];
                    a[k].x += hv * wv.x; a[k].y += hv * wv.y;
                    a[k].z += hv * wv.z; a[k].w += hv * wv.w;
                }
            }
        }

#pragma unroll
        for (int k = 0; k < NU; ++k) {
            float ig = sigf(a[k].x);
            float fg = sigf(a[k].y);
            float gg = tanhf_fast(a[k].z);
            float og = sigf(a[k].w);
            cst[k] = fg * cst[k] + ig * gg;
            hlast[k] = og * tanhf_fast(cst[k]);
            hs_n[r * UP + uk[k]] = hlast[k];
            if (SEQ)
                out[(rowbase + t) * (2 * U) + dir * U + uk[k]] = hlast[k];
            cx[k] = pre[k];
        }

        __syncthreads();
        float* tmp = hs_c; hs_c = hs_n; hs_n = tmp;
    }

    if (!SEQ) {
#pragma unroll
        for (int k = 0; k < NU; ++k)
            out[(b0 + r) * (2 * U) + dir * U + uk[k]] = hlast[k];
    }
}

// Final MLP head: relu(h @ d3_w + d3_b) @ cls_w + cls_b -> sigmoid. h: [B,32]
__global__ void head_kernel(const float* __restrict__ h3,
                            const float* __restrict__ d3w, const float* __restrict__ d3b,
                            const float* __restrict__ cw,  const float* __restrict__ cb,
                            float* __restrict__ out)
{
    int b = blockIdx.x * blockDim.x + threadIdx.x;
    if (b >= B_) return;

    float hv[32];
#pragma unroll
    for (int i = 0; i < 32; ++i) hv[i] = h3[b * 32 + i];

    float d[8];
#pragma unroll
    for (int j = 0; j < 8; ++j) {
        float a = d3b[j];
#pragma unroll
        for (int i = 0; i < 32; ++i) a += hv[i] * d3w[i * 8 + j];
        d[j] = a > 0.0f ? a : 0.0f;
    }
#pragma unroll
    for (int k = 0; k < 3; ++k) {
        float a = cb[k];
#pragma unroll
        for (int j = 0; j < 8; ++j) a += d[j] * cw[j * 3 + k];
        out[b * 3 + k] = 1.0f / (1.0f + expf(-a));
    }
}

static inline size_t gemm_smem(int KP) {
    int as_stride = KP + 4;
    int npair = KP / 2;
    return (size_t)(64 * as_stride) * 4 + (size_t)npair * 65 * 4 * 2;
}
static inline size_t rec2_smem(int U) {
    return (size_t)(U * 4 * U + 4 * U + 2 * 8 * (U + 4)) * sizeof(float);
}

extern "C" void kernel_launch(void* const* d_in, const int* in_sizes, int n_in,
                              void* d_out, int out_size)
{
    const float* x     = (const float*)d_in[0];
    const float* w1f_k = (const float*)d_in[1];
    const float* w1f_r = (const float*)d_in[2];
    const float* w1f_b = (const float*)d_in[3];
    const float* w1b_k = (const float*)d_in[4];
    const float* w1b_r = (const float*)d_in[5];
    const float* w1b_b = (const float*)d_in[6];
    const float* w2f_k = (const float*)d_in[7];
    const float* w2f_r = (const float*)d_in[8];
    const float* w2f_b = (const float*)d_in[9];
    const float* w2b_k = (const float*)d_in[10];
    const float* w2b_r = (const float*)d_in[11];
    const float* w2b_b = (const float*)d_in[12];
    const float* w3f_k = (const float*)d_in[13];
    const float* w3f_r = (const float*)d_in[14];
    const float* w3f_b = (const float*)d_in[15];
    const float* w3b_k = (const float*)d_in[16];
    const float* w3b_r = (const float*)d_in[17];
    const float* w3b_b = (const float*)d_in[18];
    const float* d3_w  = (const float*)d_in[19];
    const float* d3_b  = (const float*)d_in[20];
    const float* cls_w = (const float*)d_in[21];
    const float* cls_b = (const float*)d_in[22];

    float *b1, *b2, *b3, *xzf, *xzb;
    cudaGetSymbolAddress((void**)&b1, g_buf1);
    cudaGetSymbolAddress((void**)&b2, g_buf2);
    cudaGetSymbolAddress((void**)&b3, g_buf3);
    cudaGetSymbolAddress((void**)&xzf, g_xzf);
    cudaGetSymbolAddress((void**)&xzb, g_xzb);

    const size_t gs1 = gemm_smem(80);    // K=78
    const size_t gs2 = gemm_smem(128);
    const size_t gs3 = gemm_smem(64);
    const size_t rs1 = rec2_smem(64);    // ~70 KB
    const size_t rs2 = rec2_smem(32);    // ~18 KB
    const size_t rs3 = rec2_smem(16);    // ~5 KB

    cudaFuncSetAttribute((const void*)inproj_gemm<78, 80, 256>,
                         cudaFuncAttributeMaxDynamicSharedMemorySize, (int)gs1);
    cudaFuncSetAttribute((const void*)inproj_gemm<128, 128, 128>,
                         cudaFuncAttributeMaxDynamicSharedMemorySize, (int)gs2);
    cudaFuncSetAttribute((const void*)inproj_gemm<64, 64, 64>,
                         cudaFuncAttributeMaxDynamicSharedMemorySize, (int)gs3);
    cudaFuncSetAttribute((const void*)lstm_rec2<64, 2, true>,
                         cudaFuncAttributeMaxDynamicSharedMemorySize, (int)rs1);
    cudaFuncSetAttribute((const void*)lstm_rec2<32, 1, true>,
                         cudaFuncAttributeMaxDynamicSharedMemorySize, (int)rs2);
    cudaFuncSetAttribute((const void*)lstm_rec2<16, 1, false>,
                         cudaFuncAttributeMaxDynamicSharedMemorySize, (int)rs3);

    // ---- Layer 1 ----  U=64: NU=2 -> 8 warps, 256 thr, grid (128,2)
    inproj_gemm<78, 80, 256><<<dim3(MX_ / 64, 256 / 64, 2), 128, gs1>>>(
        x, w1f_k, w1b_k, xzf, xzb);
    lstm_rec2<64, 2, true><<<dim3(B_ / 8, 2), 256, rs1>>>(
        xzf, xzb, w1f_r, w1f_b, w1b_r, w1b_b, b1);

    // ---- Layer 2 ----  U=32: NU=1 -> 8 warps, 256 thr, grid (128,2)
    inproj_gemm<128, 128, 128><<<dim3(MX_ / 64, 128 / 64, 2), 128, gs2>>>(
        b1, w2f_k, w2b_k, xzf, xzb);
    lstm_rec2<32, 1, true><<<dim3(B_ / 8, 2), 256, rs2>>>(
        xzf, xzb, w2f_r, w2f_b, w2b_r, w2b_b, b2);

    // ---- Layer 3 ----  U=16: NU=1 -> 4 warps, 128 thr, grid (128,2)
    inproj_gemm<64, 64, 64><<<dim3(MX_ / 64, 64 / 64, 2), 128, gs3>>>(
        b2, w3f_k, w3b_k, xzf, xzb);
    lstm_rec2<16, 1, false><<<dim3(B_ / 8, 2), 128, rs3>>>(
        xzf, xzb, w3f_r, w3f_b, w3b_r, w3b_b, b3);

    // ---- Head ----
    head_kernel<<<(B_ + 255) / 256, 256>>>(b3, d3_w, d3_b, cls_w, cls_b, (float*)d_out);
}

// round 6
// speedup vs baseline: 1.1959x; 1.1959x over previous
#include <cuda_runtime.h>
#include <cuda_bf16.h>
#include <math.h>
#include <stdint.h>

// Problem-fixed shapes
#define B_ 1024
#define T_ 128
#define MX_ (B_ * T_)

// Inter-layer activation buffers + input-projection scratch (allocation-free).
__device__ float g_buf1[MX_ * 128];      // layer1 out [B,T,128]
__device__ float g_buf2[MX_ * 64];       // layer2 out [B,T,64]
__device__ float g_buf3[B_ * 32];        // layer3 out [B,32]
__device__ float g_xzf[MX_ * 256];       // fwd input projection (natural gate-major)
__device__ float g_xzb[MX_ * 256];       // bwd input projection

__device__ __forceinline__ float sigf(float x) {
    return __fdividef(1.0f, 1.0f + __expf(-x));
}
__device__ __forceinline__ float tanhf_fast(float x) {
    return __fdividef(2.0f, 1.0f + __expf(-2.0f * x)) - 1.0f;
}

// ---------------------------------------------------------------------------
// Split-bf16 GEMM on tensor cores: C = X @ W + bias, 3-term split (fp32-grade).
// Natural [MX, NGL] gate-major output, coalesced float2 stores (R4-validated).
// ---------------------------------------------------------------------------
__device__ __forceinline__ uint32_t pack_split(float v0, float v1, uint32_t& lo) {
    __nv_bfloat16 h0 = __float2bfloat16(v0);
    __nv_bfloat16 h1 = __float2bfloat16(v1);
    float r0 = v0 - __bfloat162float(h0);
    float r1 = v1 - __bfloat162float(h1);
    __nv_bfloat16 l0 = __float2bfloat16(r0);
    __nv_bfloat16 l1 = __float2bfloat16(r1);
    lo = ((uint32_t)__bfloat16_as_ushort(l1) << 16) | (uint32_t)__bfloat16_as_ushort(l0);
    return ((uint32_t)__bfloat16_as_ushort(h1) << 16) | (uint32_t)__bfloat16_as_ushort(h0);
}

__device__ __forceinline__ void mma_bf16(float* c, const uint32_t* a, uint32_t b0, uint32_t b1) {
    asm volatile(
        "mma.sync.aligned.m16n8k16.row.col.f32.bf16.bf16.f32 "
        "{%0,%1,%2,%3}, {%4,%5,%6,%7}, {%8,%9}, {%0,%1,%2,%3};\n"
        : "+f"(c[0]), "+f"(c[1]), "+f"(c[2]), "+f"(c[3])
        : "r"(a[0]), "r"(a[1]), "r"(a[2]), "r"(a[3]), "r"(b0), "r"(b1));
}

template <int K, int KP, int NGL>
__global__ void __launch_bounds__(128) inproj_gemm(
    const float* __restrict__ X,     // [MX, K]
    const float* __restrict__ Wf, const float* __restrict__ bfv,
    const float* __restrict__ Wb, const float* __restrict__ bbv,
    float* __restrict__ outf, float* __restrict__ outb)
{
    constexpr int AS_STRIDE = KP + 4;
    constexpr int NPAIR = KP / 2;
    constexpr int WS = 65;

    extern __shared__ float smraw[];
    float* As = smraw;                                   // 64 * AS_STRIDE
    uint32_t* Whi = (uint32_t*)(As + 64 * AS_STRIDE);    // NPAIR * WS
    uint32_t* Wlo = Whi + NPAIR * WS;

    const float* W    = blockIdx.z ? Wb  : Wf;
    const float* bias = blockIdx.z ? bbv : bfv;
    float* out = blockIdx.z ? outb : outf;
    const int m0 = blockIdx.x * 64;
    const int n0 = blockIdx.y * 64;
    const int tid = threadIdx.x;

    for (int i = tid; i < 64 * KP; i += 128) {
        int r = i / KP, c = i % KP;
        As[r * AS_STRIDE + c] = (c < K) ? X[(size_t)(m0 + r) * K + c] : 0.0f;
    }
    for (int i = tid; i < NPAIR * 64; i += 128) {
        int mp = i / 64, n = i % 64;
        int k0 = 2 * mp, k1 = 2 * mp + 1;
        float w0 = (k0 < K) ? W[(size_t)k0 * NGL + n0 + n] : 0.0f;
        float w1 = (k1 < K) ? W[(size_t)k1 * NGL + n0 + n] : 0.0f;
        uint32_t lo;
        uint32_t hi = pack_split(w0, w1, lo);
        Whi[mp * WS + n] = hi;
        Wlo[mp * WS + n] = lo;
    }
    __syncthreads();

    const int wid = tid >> 5, lane = tid & 31;
    const int g = lane >> 2, i4 = lane & 3;
    const int mrow = wid * 16;

    float acc[8][4];
#pragma unroll
    for (int nt = 0; nt < 8; ++nt)
#pragma unroll
        for (int q = 0; q < 4; ++q) acc[nt][q] = 0.0f;

#pragma unroll
    for (int kc = 0; kc < KP / 16; ++kc) {
        uint32_t ahi[4], alo[4];
#pragma unroll
        for (int fi = 0; fi < 4; ++fi) {
            int r = mrow + g + (fi & 1) * 8;
            int kk = kc * 16 + 2 * i4 + (fi >> 1) * 8;
            float v0 = As[r * AS_STRIDE + kk];
            float v1 = As[r * AS_STRIDE + kk + 1];
            ahi[fi] = pack_split(v0, v1, alo[fi]);
        }
#pragma unroll
        for (int nt = 0; nt < 8; ++nt) {
            int nn = nt * 8 + g;
            uint32_t bh0 = Whi[(kc * 8 + i4) * WS + nn];
            uint32_t bh1 = Whi[(kc * 8 + 4 + i4) * WS + nn];
            uint32_t bl0 = Wlo[(kc * 8 + i4) * WS + nn];
            uint32_t bl1 = Wlo[(kc * 8 + 4 + i4) * WS + nn];
            mma_bf16(acc[nt], ahi, bh0, bh1);
            mma_bf16(acc[nt], ahi, bl0, bl1);
            mma_bf16(acc[nt], alo, bh0, bh1);
        }
    }

#pragma unroll
    for (int nt = 0; nt < 8; ++nt) {
        int n = n0 + nt * 8 + 2 * i4;
        float bx = bias[n], by = bias[n + 1];
        size_t r = (size_t)(m0 + mrow + g);
        *(float2*)&out[r * NGL + n]       = make_float2(acc[nt][0] + bx, acc[nt][1] + by);
        *(float2*)&out[(r + 8) * NGL + n] = make_float2(acc[nt][2] + bx, acc[nt][3] + by);
    }
}

// ---------------------------------------------------------------------------
// L1 recurrence (U=64): 4-warp team per 2 batch rows. Warp (uh, kh): uh = unit
// half, kh = u2 half. lane's unit u = uh*32+lane; weights (4 gates x 32 u2)
// live in 128 registers. h in block SMEM, read as uniform-broadcast LDS.128.
// kh=1 warps pass partial sums through SMEM; kh=0 warps finish gates.
// 2 __syncthreads per step (4 warps only). grid (B/2, 2), block 128.
// ---------------------------------------------------------------------------
__global__ void __launch_bounds__(128) lstm_rec_l1(
    const float* __restrict__ xzf, const float* __restrict__ xzb,  // [MX, 256]
    const float* __restrict__ Wrf, const float* __restrict__ Wrb,  // [64, 256]
    float* __restrict__ out)                                        // [B, T, 128]
{
    __shared__ float  hsm[2][64];    // [row][unit]
    __shared__ float4 ps[2][64];     // kh=1 partials [row][unit]

    const int dir = blockIdx.y;
    const float* Wr = dir ? Wrb : Wrf;
    const float* xz = dir ? xzb : xzf;

    const int tid = threadIdx.x, wid = tid >> 5, lane = tid & 31;
    const int uh = wid & 1, kh = wid >> 1;
    const int u = uh * 32 + lane;
    const size_t rb0 = (size_t)(blockIdx.x * 2) * T_;
    const size_t rb1 = rb0 + T_;

    // Register-resident weights: wq[j] = gates(i,f,g,o) of Wr[kh*32+j][.] at unit u
    float4 wq[32];
#pragma unroll
    for (int j = 0; j < 32; ++j) {
        const float* wrow = Wr + (kh * 32 + j) * 256;
        wq[j] = make_float4(wrow[u], wrow[64 + u], wrow[128 + u], wrow[192 + u]);
    }

    ((float*)hsm)[tid] = 0.0f;   // 128 floats, exactly covered

    float c0 = 0.0f, c1 = 0.0f;
    float4 cx0, cx1;
    if (kh == 0) {
        const int t0 = dir ? (T_ - 1) : 0;
        const float* p0 = xz + (rb0 + t0) * 256;
        const float* p1 = xz + (rb1 + t0) * 256;
        cx0 = make_float4(p0[u], p0[64 + u], p0[128 + u], p0[192 + u]);
        cx1 = make_float4(p1[u], p1[64 + u], p1[128 + u], p1[192 + u]);
    }
    __syncthreads();

    for (int s = 0; s < T_; ++s) {
        const int t  = dir ? (T_ - 1 - s) : s;
        const int sn = (s + 1 < T_) ? (s + 1) : s;
        const int tn = dir ? (T_ - 1 - sn) : sn;

        float4 pre0, pre1;
        if (kh == 0) {
            const float* p0 = xz + (rb0 + tn) * 256;
            const float* p1 = xz + (rb1 + tn) * 256;
            pre0 = make_float4(p0[u], p0[64 + u], p0[128 + u], p0[192 + u]);
            pre1 = make_float4(p1[u], p1[64 + u], p1[128 + u], p1[192 + u]);
        }

        float4 a0 = make_float4(0, 0, 0, 0), a1 = make_float4(0, 0, 0, 0);
#pragma unroll
        for (int j = 0; j < 8; ++j) {
            float4 h40 = *(const float4*)&hsm[0][kh * 32 + j * 4];
            float4 h41 = *(const float4*)&hsm[1][kh * 32 + j * 4];
#pragma unroll
            for (int q = 0; q < 4; ++q) {
                float hv0 = (&h40.x)[q], hv1 = (&h41.x)[q];
                float4 w = wq[j * 4 + q];
                a0.x += hv0 * w.x; a0.y += hv0 * w.y; a0.z += hv0 * w.z; a0.w += hv0 * w.w;
                a1.x += hv1 * w.x; a1.y += hv1 * w.y; a1.z += hv1 * w.z; a1.w += hv1 * w.w;
            }
        }
        if (kh == 1) { ps[0][u] = a0; ps[1][u] = a1; }
        __syncthreads();

        if (kh == 0) {
            float4 q0 = ps[0][u], q1 = ps[1][u];
            float i0 = sigf(a0.x + q0.x + cx0.x);
            float f0 = sigf(a0.y + q0.y + cx0.y);
            float g0 = tanhf_fast(a0.z + q0.z + cx0.z);
            float o0 = sigf(a0.w + q0.w + cx0.w);
            c0 = f0 * c0 + i0 * g0;
            float h0n = o0 * tanhf_fast(c0);
            float i1 = sigf(a1.x + q1.x + cx1.x);
            float f1 = sigf(a1.y + q1.y + cx1.y);
            float g1 = tanhf_fast(a1.z + q1.z + cx1.z);
            float o1 = sigf(a1.w + q1.w + cx1.w);
            c1 = f1 * c1 + i1 * g1;
            float h1n = o1 * tanhf_fast(c1);
            hsm[0][u] = h0n;
            hsm[1][u] = h1n;
            out[(rb0 + t) * 128 + dir * 64 + u] = h0n;
            out[(rb1 + t) * 128 + dir * 64 + u] = h1n;
            cx0 = pre0; cx1 = pre1;
        }
        __syncthreads();
    }
}

// ---------------------------------------------------------------------------
// L2 recurrence (U=32): sync-free warp-per-2-rows. lane = unit; Wr columns in
// 128 registers; h staged through per-warp parity-buffered SMEM read as
// uniform-broadcast LDS.128; one __syncwarp per step. grid (B/8, 2), block 128.
// ---------------------------------------------------------------------------
__global__ void __launch_bounds__(128) lstm_rec_l2(
    const float* __restrict__ xzf, const float* __restrict__ xzb,  // [MX, 128]
    const float* __restrict__ Wrf, const float* __restrict__ Wrb,  // [32, 128]
    float* __restrict__ out)                                        // [B, T, 64]
{
    __shared__ float hsm[4][2][2][32];   // [warp][parity][row][unit]

    const int dir = blockIdx.y;
    const float* Wr = dir ? Wrb : Wrf;
    const float* xz = dir ? xzb : xzf;

    const int tid = threadIdx.x, wid = tid >> 5, lane = tid & 31;
    const size_t rb0 = (size_t)(blockIdx.x * 8 + wid * 2) * T_;
    const size_t rb1 = rb0 + T_;

    float4 wq[32];
#pragma unroll
    for (int u2 = 0; u2 < 32; ++u2) {
        const float* wrow = Wr + u2 * 128;
        wq[u2] = make_float4(wrow[lane], wrow[32 + lane], wrow[64 + lane], wrow[96 + lane]);
    }

    float c0 = 0.0f, c1 = 0.0f;
    float4 cx0, cx1;
    {
        const int t0 = dir ? (T_ - 1) : 0;
        const float* p0 = xz + (rb0 + t0) * 128;
        const float* p1 = xz + (rb1 + t0) * 128;
        cx0 = make_float4(p0[lane], p0[32 + lane], p0[64 + lane], p0[96 + lane]);
        cx1 = make_float4(p1[lane], p1[32 + lane], p1[64 + lane], p1[96 + lane]);
    }
    hsm[wid][0][0][lane] = 0.0f;
    hsm[wid][0][1][lane] = 0.0f;
    __syncwarp();

    int p = 0;
    for (int s = 0; s < T_; ++s) {
        const int t  = dir ? (T_ - 1 - s) : s;
        const int sn = (s + 1 < T_) ? (s + 1) : s;
        const int tn = dir ? (T_ - 1 - sn) : sn;

        const float* q0 = xz + (rb0 + tn) * 128;
        const float* q1 = xz + (rb1 + tn) * 128;
        float4 pre0 = make_float4(q0[lane], q0[32 + lane], q0[64 + lane], q0[96 + lane]);
        float4 pre1 = make_float4(q1[lane], q1[32 + lane], q1[64 + lane], q1[96 + lane]);

        float4 a0 = cx0, a1 = cx1;
#pragma unroll
        for (int j = 0; j < 8; ++j) {
            float4 h40 = *(const float4*)&hsm[wid][p][0][j * 4];
            float4 h41 = *(const float4*)&hsm[wid][p][1][j * 4];
#pragma unroll
            for (int q = 0; q < 4; ++q) {
                float hv0 = (&h40.x)[q], hv1 = (&h41.x)[q];
                float4 w = wq[j * 4 + q];
                a0.x += hv0 * w.x; a0.y += hv0 * w.y; a0.z += hv0 * w.z; a0.w += hv0 * w.w;
                a1.x += hv1 * w.x; a1.y += hv1 * w.y; a1.z += hv1 * w.z; a1.w += hv1 * w.w;
            }
        }

        float i0 = sigf(a0.x), f0 = sigf(a0.y), g0 = tanhf_fast(a0.z), o0 = sigf(a0.w);
        c0 = f0 * c0 + i0 * g0;
        float h0 = o0 * tanhf_fast(c0);
        float i1 = sigf(a1.x), f1 = sigf(a1.y), g1 = tanhf_fast(a1.z), o1 = sigf(a1.w);
        c1 = f1 * c1 + i1 * g1;
        float h1 = o1 * tanhf_fast(c1);

        hsm[wid][p ^ 1][0][lane] = h0;
        hsm[wid][p ^ 1][1][lane] = h1;
        out[(rb0 + t) * 64 + dir * 32 + lane] = h0;
        out[(rb1 + t) * 64 + dir * 32 + lane] = h1;
        cx0 = pre0; cx1 = pre1;
        __syncwarp();
        p ^= 1;
    }
}

// ---------------------------------------------------------------------------
// L3 recurrence (U=16): warp handles 4 rows (lane halves x 2 register rows).
// lane = (r2, u). Weights 64 regs. Last-step output only. grid (B/16, 2).
// ---------------------------------------------------------------------------
__global__ void __launch_bounds__(128) lstm_rec_l3(
    const float* __restrict__ xzf, const float* __restrict__ xzb,  // [MX, 64]
    const float* __restrict__ Wrf, const float* __restrict__ Wrb,  // [16, 64]
    float* __restrict__ out)                                        // [B, 32]
{
    __shared__ float hsm[4][2][4][16];   // [warp][parity][row][unit]

    const int dir = blockIdx.y;
    const float* Wr = dir ? Wrb : Wrf;
    const float* xz = dir ? xzb : xzf;

    const int tid = threadIdx.x, wid = tid >> 5, lane = tid & 31;
    const int r2 = lane >> 4, u = lane & 15;
    const int ra = blockIdx.x * 16 + wid * 4 + r2 * 2;   // first of this lane's 2 rows
    const size_t rba = (size_t)ra * T_;
    const size_t rbb = rba + T_;

    float4 wq[16];
#pragma unroll
    for (int u2 = 0; u2 < 16; ++u2) {
        const float* wrow = Wr + u2 * 64;
        wq[u2] = make_float4(wrow[u], wrow[16 + u], wrow[32 + u], wrow[48 + u]);
    }

    float ca = 0.0f, cb = 0.0f, ha = 0.0f, hb = 0.0f;
    float4 cxa, cxb;
    {
        const int t0 = dir ? (T_ - 1) : 0;
        const float* p0 = xz + (rba + t0) * 64;
        const float* p1 = xz + (rbb + t0) * 64;
        cxa = make_float4(p0[u], p0[16 + u], p0[32 + u], p0[48 + u]);
        cxb = make_float4(p1[u], p1[16 + u], p1[32 + u], p1[48 + u]);
    }
    hsm[wid][0][r2 * 2][u] = 0.0f;
    hsm[wid][0][r2 * 2 + 1][u] = 0.0f;
    __syncwarp();

    int p = 0;
    for (int s = 0; s < T_; ++s) {
        const int sn = (s + 1 < T_) ? (s + 1) : s;
        const int tn = dir ? (T_ - 1 - sn) : sn;

        const float* q0 = xz + (rba + tn) * 64;
        const float* q1 = xz + (rbb + tn) * 64;
        float4 prea = make_float4(q0[u], q0[16 + u], q0[32 + u], q0[48 + u]);
        float4 preb = make_float4(q1[u], q1[16 + u], q1[32 + u], q1[48 + u]);

        float4 aa = cxa, ab = cxb;
#pragma unroll
        for (int j = 0; j < 4; ++j) {
            float4 h4a = *(const float4*)&hsm[wid][p][r2 * 2][j * 4];
            float4 h4b = *(const float4*)&hsm[wid][p][r2 * 2 + 1][j * 4];
#pragma unroll
            for (int q = 0; q < 4; ++q) {
                float hva = (&h4a.x)[q], hvb = (&h4b.x)[q];
                float4 w = wq[j * 4 + q];
                aa.x += hva * w.x; aa.y += hva * w.y; aa.z += hva * w.z; aa.w += hva * w.w;
                ab.x += hvb * w.x; ab.y += hvb * w.y; ab.z += hvb * w.z; ab.w += hvb * w.w;
            }
        }

        float ia = sigf(aa.x), fa = sigf(aa.y), ga = tanhf_fast(aa.z), oa = sigf(aa.w);
        ca = fa * ca + ia * ga;
        ha = oa * tanhf_fast(ca);
        float ib = sigf(ab.x), fb = sigf(ab.y), gb = tanhf_fast(ab.z), ob = sigf(ab.w);
        cb = fb * cb + ib * gb;
        hb = ob * tanhf_fast(cb);

        hsm[wid][p ^ 1][r2 * 2][u] = ha;
        hsm[wid][p ^ 1][r2 * 2 + 1][u] = hb;
        cxa = prea; cxb = preb;
        __syncwarp();
        p ^= 1;
    }

    out[ra * 32 + dir * 16 + u] = ha;
    out[(ra + 1) * 32 + dir * 16 + u] = hb;
}

// Final MLP head.
__global__ void head_kernel(const float* __restrict__ h3,
                            const float* __restrict__ d3w, const float* __restrict__ d3b,
                            const float* __restrict__ cw,  const float* __restrict__ cb,
                            float* __restrict__ out)
{
    int b = blockIdx.x * blockDim.x + threadIdx.x;
    if (b >= B_) return;

    float hv[32];
#pragma unroll
    for (int i = 0; i < 32; ++i) hv[i] = h3[b * 32 + i];

    float d[8];
#pragma unroll
    for (int j = 0; j < 8; ++j) {
        float a = d3b[j];
#pragma unroll
        for (int i = 0; i < 32; ++i) a += hv[i] * d3w[i * 8 + j];
        d[j] = a > 0.0f ? a : 0.0f;
    }
#pragma unroll
    for (int k = 0; k < 3; ++k) {
        float a = cb[k];
#pragma unroll
        for (int j = 0; j < 8; ++j) a += d[j] * cw[j * 3 + k];
        out[b * 3 + k] = 1.0f / (1.0f + expf(-a));
    }
}

static inline size_t gemm_smem(int KP) {
    int as_stride = KP + 4;
    int npair = KP / 2;
    return (size_t)(64 * as_stride) * 4 + (size_t)npair * 65 * 4 * 2;
}

extern "C" void kernel_launch(void* const* d_in, const int* in_sizes, int n_in,
                              void* d_out, int out_size)
{
    const float* x     = (const float*)d_in[0];
    const float* w1f_k = (const float*)d_in[1];
    const float* w1f_r = (const float*)d_in[2];
    const float* w1f_b = (const float*)d_in[3];
    const float* w1b_k = (const float*)d_in[4];
    const float* w1b_r = (const float*)d_in[5];
    const float* w1b_b = (const float*)d_in[6];
    const float* w2f_k = (const float*)d_in[7];
    const float* w2f_r = (const float*)d_in[8];
    const float* w2f_b = (const float*)d_in[9];
    const float* w2b_k = (const float*)d_in[10];
    const float* w2b_r = (const float*)d_in[11];
    const float* w2b_b = (const float*)d_in[12];
    const float* w3f_k = (const float*)d_in[13];
    const float* w3f_r = (const float*)d_in[14];
    const float* w3f_b = (const float*)d_in[15];
    const float* w3b_k = (const float*)d_in[16];
    const float* w3b_r = (const float*)d_in[17];
    const float* w3b_b = (const float*)d_in[18];
    const float* d3_w  = (const float*)d_in[19];
    const float* d3_b  = (const float*)d_in[20];
    const float* cls_w = (const float*)d_in[21];
    const float* cls_b = (const float*)d_in[22];

    float *b1, *b2, *b3, *xzf, *xzb;
    cudaGetSymbolAddress((void**)&b1, g_buf1);
    cudaGetSymbolAddress((void**)&b2, g_buf2);
    cudaGetSymbolAddress((void**)&b3, g_buf3);
    cudaGetSymbolAddress((void**)&xzf, g_xzf);
    cudaGetSymbolAddress((void**)&xzb, g_xzb);

    const size_t gs1 = gemm_smem(80);
    const size_t gs2 = gemm_smem(128);
    const size_t gs3 = gemm_smem(64);

    cudaFuncSetAttribute((const void*)inproj_gemm<78, 80, 256>,
                         cudaFuncAttributeMaxDynamicSharedMemorySize, (int)gs1);
    cudaFuncSetAttribute((const void*)inproj_gemm<128, 128, 128>,
                         cudaFuncAttributeMaxDynamicSharedMemorySize, (int)gs2);
    cudaFuncSetAttribute((const void*)inproj_gemm<64, 64, 64>,
                         cudaFuncAttributeMaxDynamicSharedMemorySize, (int)gs3);

    // ---- Layer 1 ----
    inproj_gemm<78, 80, 256><<<dim3(MX_ / 64, 4, 2), 128, gs1>>>(
        x, w1f_k, w1f_b, w1b_k, w1b_b, xzf, xzb);
    lstm_rec_l1<<<dim3(B_ / 2, 2), 128>>>(xzf, xzb, w1f_r, w1b_r, b1);

    // ---- Layer 2 ----
    inproj_gemm<128, 128, 128><<<dim3(MX_ / 64, 2, 2), 128, gs2>>>(
        b1, w2f_k, w2f_b, w2b_k, w2b_b, xzf, xzb);
    lstm_rec_l2<<<dim3(B_ / 8, 2), 128>>>(xzf, xzb, w2f_r, w2b_r, b2);

    // ---- Layer 3 ----
    inproj_gemm<64, 64, 64><<<dim3(MX_ / 64, 1, 2), 128, gs3>>>(
        b2, w3f_k, w3f_b, w3b_k, w3b_b, xzf, xzb);
    lstm_rec_l3<<<dim3(B_ / 16, 2), 128>>>(xzf, xzb, w3f_r, w3b_r, b3);

    // ---- Head ----
    head_kernel<<<(B_ + 255) / 256, 256>>>(b3, d3_w, d3_b, cls_w, cls_b, (float*)d_out);
}

// round 7
// speedup vs baseline: 1.5880x; 1.3278x over previous
#include <cuda_runtime.h>
#include <cuda_bf16.h>
#include <math.h>
#include <stdint.h>

#define B_ 1024
#define T_ 128
#define MX_ (B_ * T_)

__device__ float g_buf1[MX_ * 128];
__device__ float g_buf2[MX_ * 64];
__device__ float g_buf3[B_ * 32];
__device__ float g_xzf[MX_ * 256];
__device__ float g_xzb[MX_ * 256];

__device__ __forceinline__ float sigf(float x) {
    return __fdividef(1.0f, 1.0f + __expf(-x));
}
__device__ __forceinline__ float tanhf_fast(float x) {
    return __fdividef(2.0f, 1.0f + __expf(-2.0f * x)) - 1.0f;
}

// ---------------------------------------------------------------------------
// Split-bf16 GEMM v3: C = X @ W + bias (fp32-grade via hi*hi + hi*lo + lo*hi).
// Block 256 thr: M-tile 128 x full NGL. A/W pre-packed to bf16 hi/lo u32 pairs
// in SMEM once. Each warp owns an N-slice, caches ALL its B fragments in
// registers, then loops 8 M-tiles with a small accumulator.
// grid = (MX/128, 2 dirs).
// ---------------------------------------------------------------------------
__device__ __forceinline__ uint32_t pack_split(float v0, float v1, uint32_t& lo) {
    __nv_bfloat16 h0 = __float2bfloat16(v0);
    __nv_bfloat16 h1 = __float2bfloat16(v1);
    float r0 = v0 - __bfloat162float(h0);
    float r1 = v1 - __bfloat162float(h1);
    __nv_bfloat16 l0 = __float2bfloat16(r0);
    __nv_bfloat16 l1 = __float2bfloat16(r1);
    lo = ((uint32_t)__bfloat16_as_ushort(l1) << 16) | (uint32_t)__bfloat16_as_ushort(l0);
    return ((uint32_t)__bfloat16_as_ushort(h1) << 16) | (uint32_t)__bfloat16_as_ushort(h0);
}

__device__ __forceinline__ void mma_bf16(float* c, const uint32_t* a, uint32_t b0, uint32_t b1) {
    asm volatile(
        "mma.sync.aligned.m16n8k16.row.col.f32.bf16.bf16.f32 "
        "{%0,%1,%2,%3}, {%4,%5,%6,%7}, {%8,%9}, {%0,%1,%2,%3};\n"
        : "+f"(c[0]), "+f"(c[1]), "+f"(c[2]), "+f"(c[3])
        : "r"(a[0]), "r"(a[1]), "r"(a[2]), "r"(a[3]), "r"(b0), "r"(b1));
}

template <int K, int KP, int NGL, int ASTR>
__global__ void __launch_bounds__(256, 1) inproj_gemm(
    const float* __restrict__ X,
    const float* __restrict__ Wf, const float* __restrict__ bfv,
    const float* __restrict__ Wb, const float* __restrict__ bbv,
    float* __restrict__ outf, float* __restrict__ outb)
{
    constexpr int KPH = KP / 2;          // k-pairs
    constexpr int KC  = KP / 16;         // k-chunks of 16
    constexpr int WS  = NGL + 1;         // padded W stride
    constexpr int NTW = NGL / 64;        // n-tiles per warp (slice NGL/8, tiles of 8)

    extern __shared__ uint32_t smu[];
    uint32_t* Ahi = smu;                         // 128 * ASTR
    uint32_t* Alo = Ahi + 128 * ASTR;            // 128 * ASTR
    uint32_t* Whi = Alo + 128 * ASTR;            // KPH * WS
    uint32_t* Wlo = Whi + KPH * WS;              // KPH * WS

    const int dir = blockIdx.y;
    const float* W    = dir ? Wb  : Wf;
    const float* bias = dir ? bbv : bfv;
    float* out = dir ? outb : outf;
    const int m0 = blockIdx.x * 128;
    const int tid = threadIdx.x;

    // Stage A packed (float2 global reads, K even for all layers)
    for (int i = tid; i < 128 * KPH; i += 256) {
        int row = i / KPH, pp = i % KPH;
        int k0 = 2 * pp;
        float v0 = 0.0f, v1 = 0.0f;
        if (k0 < K) {
            float2 xv = *(const float2*)&X[(size_t)(m0 + row) * K + k0];
            v0 = xv.x; v1 = xv.y;
        }
        uint32_t lo;
        uint32_t hi = pack_split(v0, v1, lo);
        Ahi[row * ASTR + pp] = hi;
        Alo[row * ASTR + pp] = lo;
    }
    // Stage W packed
    for (int i = tid; i < KPH * NGL; i += 256) {
        int pp = i / NGL, n = i % NGL;
        int k0 = 2 * pp;
        float w0 = (k0 < K)     ? W[(size_t)k0 * NGL + n]       : 0.0f;
        float w1 = (k0 + 1 < K) ? W[(size_t)(k0 + 1) * NGL + n] : 0.0f;
        uint32_t lo;
        uint32_t hi = pack_split(w0, w1, lo);
        Whi[pp * WS + n] = hi;
        Wlo[pp * WS + n] = lo;
    }
    __syncthreads();

    const int wid = tid >> 5, lane = tid & 31;
    const int g = lane >> 2, i4 = lane & 3;
    const int n0 = wid * (NGL / 8);

    // Cache B fragments in registers (whole K, this warp's N-slice)
    uint32_t bh0c[KC][NTW], bh1c[KC][NTW], bl0c[KC][NTW], bl1c[KC][NTW];
#pragma unroll
    for (int kc = 0; kc < KC; ++kc)
#pragma unroll
        for (int nt = 0; nt < NTW; ++nt) {
            int nn = n0 + nt * 8 + g;
            bh0c[kc][nt] = Whi[(kc * 8 + i4) * WS + nn];
            bh1c[kc][nt] = Whi[(kc * 8 + 4 + i4) * WS + nn];
            bl0c[kc][nt] = Wlo[(kc * 8 + i4) * WS + nn];
            bl1c[kc][nt] = Wlo[(kc * 8 + 4 + i4) * WS + nn];
        }

#pragma unroll
    for (int mt = 0; mt < 8; ++mt) {
        const int mrow = mt * 16;
        float acc[NTW][4];
#pragma unroll
        for (int nt = 0; nt < NTW; ++nt)
#pragma unroll
            for (int q = 0; q < 4; ++q) acc[nt][q] = 0.0f;

#pragma unroll
        for (int kc = 0; kc < KC; ++kc) {
            uint32_t ahi[4], alo[4];
#pragma unroll
            for (int fi = 0; fi < 4; ++fi) {
                int r = mrow + g + (fi & 1) * 8;
                int pp = kc * 8 + i4 + (fi >> 1) * 4;
                ahi[fi] = Ahi[r * ASTR + pp];
                alo[fi] = Alo[r * ASTR + pp];
            }
#pragma unroll
            for (int nt = 0; nt < NTW; ++nt) {
                mma_bf16(acc[nt], ahi, bh0c[kc][nt], bh1c[kc][nt]);
                mma_bf16(acc[nt], ahi, bl0c[kc][nt], bl1c[kc][nt]);
                mma_bf16(acc[nt], alo, bh0c[kc][nt], bh1c[kc][nt]);
            }
        }

#pragma unroll
        for (int nt = 0; nt < NTW; ++nt) {
            int n = n0 + nt * 8 + 2 * i4;
            float bx = bias[n], by = bias[n + 1];
            size_t r = (size_t)(m0 + mrow + g);
            *(float2*)&out[r * NGL + n]       = make_float2(acc[nt][0] + bx, acc[nt][1] + by);
            *(float2*)&out[(r + 8) * NGL + n] = make_float2(acc[nt][2] + bx, acc[nt][3] + by);
        }
    }
}

// ---------------------------------------------------------------------------
// L1 recurrence (U=64): block 256 thr = (kh:2) x (rowgrp:2) x (unit:64),
// covers 8 rows. Thread (kh,r4g,u): partial h@Wr over its k-half for 4 rows,
// weight LDS.128 amortized over 16 FFMAs. kh=1 passes partials via SMEM;
// kh=0 finishes gates. 2 barriers/step. grid (B/8, 2) -> 2048 warps.
// ---------------------------------------------------------------------------
__global__ void __launch_bounds__(256) lstm_rec_l1(
    const float* __restrict__ xzf, const float* __restrict__ xzb,  // [MX,256]
    const float* __restrict__ Wrf, const float* __restrict__ Wrb,  // [64,256]
    float* __restrict__ out)                                        // [B,T,128]
{
    constexpr int UP = 68;
    extern __shared__ float sm[];
    float* Wr_s = sm;                    // 64*256 gate-interleaved [u2][u][4]
    float* hs0  = Wr_s + 64 * 256;       // 8*UP
    float* hs1  = hs0 + 8 * UP;          // 8*UP
    float4* ps  = (float4*)(hs1 + 8 * UP);  // [8][64]

    const int dir = blockIdx.y;
    const float* Wr = dir ? Wrb : Wrf;
    const float* xz = dir ? xzb : xzf;

    const int tid = threadIdx.x;
    const int u   = tid & 63;
    const int r0  = ((tid >> 6) & 1) * 4;
    const int kh  = tid >> 7;
    const int b0  = blockIdx.x * 8;

    for (int i = tid; i < 64 * 256; i += 256) {
        int u2 = i >> 8, c = i & 255, uu = c >> 2, gg = c & 3;
        Wr_s[i] = Wr[u2 * 256 + gg * 64 + uu];
    }
    for (int i = tid; i < 2 * 8 * UP; i += 256) hs0[i] = 0.0f;

    float cst[4], cx[4][4];
#pragma unroll
    for (int j = 0; j < 4; ++j) cst[j] = 0.0f;
    if (kh == 0) {
        const int t0 = dir ? (T_ - 1) : 0;
#pragma unroll
        for (int j = 0; j < 4; ++j) {
            const float* p = xz + ((size_t)(b0 + r0 + j) * T_ + t0) * 256;
#pragma unroll
            for (int gg = 0; gg < 4; ++gg) cx[j][gg] = p[gg * 64 + u];
        }
    }
    __syncthreads();

    const float4* __restrict__ wr4 = (const float4*)Wr_s;
    float* hs_c = hs0; float* hs_n = hs1;

    for (int s = 0; s < T_; ++s) {
        const int t  = dir ? (T_ - 1 - s) : s;
        const int sn = (s + 1 < T_) ? (s + 1) : s;
        const int tn = dir ? (T_ - 1 - sn) : sn;

        float pre[4][4];
        if (kh == 0) {
#pragma unroll
            for (int j = 0; j < 4; ++j) {
                const float* p = xz + ((size_t)(b0 + r0 + j) * T_ + tn) * 256;
#pragma unroll
                for (int gg = 0; gg < 4; ++gg) pre[j][gg] = p[gg * 64 + u];
            }
        }

        float4 a[4];
#pragma unroll
        for (int j = 0; j < 4; ++j) a[j] = make_float4(0, 0, 0, 0);

#pragma unroll
        for (int jj = 0; jj < 8; ++jj) {
            float4 h4[4];
#pragma unroll
            for (int j = 0; j < 4; ++j)
                h4[j] = *(const float4*)&hs_c[(r0 + j) * UP + kh * 32 + jj * 4];
#pragma unroll
            for (int q = 0; q < 4; ++q) {
                float4 wv = wr4[(kh * 32 + jj * 4 + q) * 64 + u];
#pragma unroll
                for (int j = 0; j < 4; ++j) {
                    float hv = (&h4[j].x)[q];
                    a[j].x += hv * wv.x; a[j].y += hv * wv.y;
                    a[j].z += hv * wv.z; a[j].w += hv * wv.w;
                }
            }
        }

        if (kh == 1) {
#pragma unroll
            for (int j = 0; j < 4; ++j) ps[(r0 + j) * 64 + u] = a[j];
        }
        __syncthreads();

        if (kh == 0) {
#pragma unroll
            for (int j = 0; j < 4; ++j) {
                float4 q4 = ps[(r0 + j) * 64 + u];
                float ig = sigf(a[j].x + q4.x + cx[j][0]);
                float fg = sigf(a[j].y + q4.y + cx[j][1]);
                float gg = tanhf_fast(a[j].z + q4.z + cx[j][2]);
                float og = sigf(a[j].w + q4.w + cx[j][3]);
                cst[j] = fg * cst[j] + ig * gg;
                float hn = og * tanhf_fast(cst[j]);
                hs_n[(r0 + j) * UP + u] = hn;
                out[((size_t)(b0 + r0 + j) * T_ + t) * 128 + dir * 64 + u] = hn;
#pragma unroll
                for (int gg2 = 0; gg2 < 4; ++gg2) cx[j][gg2] = pre[j][gg2];
            }
        }
        __syncthreads();
        float* tmp = hs_c; hs_c = hs_n; hs_n = tmp;
    }
}

// ---------------------------------------------------------------------------
// L2 recurrence (U=32): sync-free, 1 row per warp, lane = unit, weights in
// 128 registers, h via per-warp parity SMEM. grid (B/4, 2) -> 2048 warps.
// ---------------------------------------------------------------------------
__global__ void __launch_bounds__(128) lstm_rec_l2(
    const float* __restrict__ xzf, const float* __restrict__ xzb,  // [MX,128]
    const float* __restrict__ Wrf, const float* __restrict__ Wrb,  // [32,128]
    float* __restrict__ out)                                        // [B,T,64]
{
    __shared__ float hsm[4][2][32];

    const int dir = blockIdx.y;
    const float* Wr = dir ? Wrb : Wrf;
    const float* xz = dir ? xzb : xzf;

    const int tid = threadIdx.x, wid = tid >> 5, lane = tid & 31;
    const size_t rb = (size_t)(blockIdx.x * 4 + wid) * T_;

    float4 wq[32];
#pragma unroll
    for (int u2 = 0; u2 < 32; ++u2) {
        const float* wrow = Wr + u2 * 128;
        wq[u2] = make_float4(wrow[lane], wrow[32 + lane], wrow[64 + lane], wrow[96 + lane]);
    }

    float cst = 0.0f;
    float4 cx;
    {
        const int t0 = dir ? (T_ - 1) : 0;
        const float* p = xz + (rb + t0) * 128;
        cx = make_float4(p[lane], p[32 + lane], p[64 + lane], p[96 + lane]);
    }
    hsm[wid][0][lane] = 0.0f;
    __syncwarp();

    int p = 0;
    for (int s = 0; s < T_; ++s) {
        const int t  = dir ? (T_ - 1 - s) : s;
        const int sn = (s + 1 < T_) ? (s + 1) : s;
        const int tn = dir ? (T_ - 1 - sn) : sn;

        const float* q = xz + (rb + tn) * 128;
        float4 pre = make_float4(q[lane], q[32 + lane], q[64 + lane], q[96 + lane]);

        float4 a = cx;
#pragma unroll
        for (int jj = 0; jj < 8; ++jj) {
            float4 h4 = *(const float4*)&hsm[wid][p][jj * 4];
#pragma unroll
            for (int qq = 0; qq < 4; ++qq) {
                float hv = (&h4.x)[qq];
                float4 w = wq[jj * 4 + qq];
                a.x += hv * w.x; a.y += hv * w.y; a.z += hv * w.z; a.w += hv * w.w;
            }
        }

        float ig = sigf(a.x), fg = sigf(a.y), gg = tanhf_fast(a.z), og = sigf(a.w);
        cst = fg * cst + ig * gg;
        float h = og * tanhf_fast(cst);

        hsm[wid][p ^ 1][lane] = h;
        out[(rb + t) * 64 + dir * 32 + lane] = h;
        cx = pre;
        __syncwarp();
        p ^= 1;
    }
}

// ---------------------------------------------------------------------------
// L3 recurrence (U=16): 2 rows per warp (1 per lane-half), lane=(r2,u).
// grid (B/8, 2) -> 1024 warps. Last-step output only.
// ---------------------------------------------------------------------------
__global__ void __launch_bounds__(128) lstm_rec_l3(
    const float* __restrict__ xzf, const float* __restrict__ xzb,  // [MX,64]
    const float* __restrict__ Wrf, const float* __restrict__ Wrb,  // [16,64]
    float* __restrict__ out)                                        // [B,32]
{
    __shared__ float hsm[4][2][2][16];

    const int dir = blockIdx.y;
    const float* Wr = dir ? Wrb : Wrf;
    const float* xz = dir ? xzb : xzf;

    const int tid = threadIdx.x, wid = tid >> 5, lane = tid & 31;
    const int r2 = lane >> 4, u = lane & 15;
    const int row = blockIdx.x * 8 + wid * 2 + r2;
    const size_t rb = (size_t)row * T_;

    float4 wq[16];
#pragma unroll
    for (int u2 = 0; u2 < 16; ++u2) {
        const float* wrow = Wr + u2 * 64;
        wq[u2] = make_float4(wrow[u], wrow[16 + u], wrow[32 + u], wrow[48 + u]);
    }

    float cst = 0.0f, h = 0.0f;
    float4 cx;
    {
        const int t0 = dir ? (T_ - 1) : 0;
        const float* p = xz + (rb + t0) * 64;
        cx = make_float4(p[u], p[16 + u], p[32 + u], p[48 + u]);
    }
    hsm[wid][0][r2][u] = 0.0f;
    __syncwarp();

    int p = 0;
    for (int s = 0; s < T_; ++s) {
        const int sn = (s + 1 < T_) ? (s + 1) : s;
        const int tn = dir ? (T_ - 1 - sn) : sn;

        const float* q = xz + (rb + tn) * 64;
        float4 pre = make_float4(q[u], q[16 + u], q[32 + u], q[48 + u]);

        float4 a = cx;
#pragma unroll
        for (int jj = 0; jj < 4; ++jj) {
            float4 h4 = *(const float4*)&hsm[wid][p][r2][jj * 4];
#pragma unroll
            for (int qq = 0; qq < 4; ++qq) {
                float hv = (&h4.x)[qq];
                float4 w = wq[jj * 4 + qq];
                a.x += hv * w.x; a.y += hv * w.y; a.z += hv * w.z; a.w += hv * w.w;
            }
        }

        float ig = sigf(a.x), fg = sigf(a.y), gg = tanhf_fast(a.z), og = sigf(a.w);
        cst = fg * cst + ig * gg;
        h = og * tanhf_fast(cst);

        hsm[wid][p ^ 1][r2][u] = h;
        cx = pre;
        __syncwarp();
        p ^= 1;
    }

    out[row * 32 + dir * 16 + u] = h;
}

// Final MLP head.
__global__ void head_kernel(const float* __restrict__ h3,
                            const float* __restrict__ d3w, const float* __restrict__ d3b,
                            const float* __restrict__ cw,  const float* __restrict__ cb,
                            float* __restrict__ out)
{
    int b = blockIdx.x * blockDim.x + threadIdx.x;
    if (b >= B_) return;

    float hv[32];
#pragma unroll
    for (int i = 0; i < 32; ++i) hv[i] = h3[b * 32 + i];

    float d[8];
#pragma unroll
    for (int j = 0; j < 8; ++j) {
        float a = d3b[j];
#pragma unroll
        for (int i = 0; i < 32; ++i) a += hv[i] * d3w[i * 8 + j];
        d[j] = a > 0.0f ? a : 0.0f;
    }
#pragma unroll
    for (int k = 0; k < 3; ++k) {
        float a = cb[k];
#pragma unroll
        for (int j = 0; j < 8; ++j) a += d[j] * cw[j * 3 + k];
        out[b * 3 + k] = 1.0f / (1.0f + expf(-a));
    }
}

static inline size_t gemm_smem(int KP, int NGL, int ASTR) {
    return (size_t)(2 * 128 * ASTR + 2 * (KP / 2) * (NGL + 1)) * 4;
}

extern "C" void kernel_launch(void* const* d_in, const int* in_sizes, int n_in,
                              void* d_out, int out_size)
{
    const float* x     = (const float*)d_in[0];
    const float* w1f_k = (const float*)d_in[1];
    const float* w1f_r = (const float*)d_in[2];
    const float* w1f_b = (const float*)d_in[3];
    const float* w1b_k = (const float*)d_in[4];
    const float* w1b_r = (const float*)d_in[5];
    const float* w1b_b = (const float*)d_in[6];
    const float* w2f_k = (const float*)d_in[7];
    const float* w2f_r = (const float*)d_in[8];
    const float* w2f_b = (const float*)d_in[9];
    const float* w2b_k = (const float*)d_in[10];
    const float* w2b_r = (const float*)d_in[11];
    const float* w2b_b = (const float*)d_in[12];
    const float* w3f_k = (const float*)d_in[13];
    const float* w3f_r = (const float*)d_in[14];
    const float* w3f_b = (const float*)d_in[15];
    const float* w3b_k = (const float*)d_in[16];
    const float* w3b_r = (const float*)d_in[17];
    const float* w3b_b = (const float*)d_in[18];
    const float* d3_w  = (const float*)d_in[19];
    const float* d3_b  = (const float*)d_in[20];
    const float* cls_w = (const float*)d_in[21];
    const float* cls_b = (const float*)d_in[22];

    float *b1, *b2, *b3, *xzf, *xzb;
    cudaGetSymbolAddress((void**)&b1, g_buf1);
    cudaGetSymbolAddress((void**)&b2, g_buf2);
    cudaGetSymbolAddress((void**)&b3, g_buf3);
    cudaGetSymbolAddress((void**)&xzf, g_xzf);
    cudaGetSymbolAddress((void**)&xzb, g_xzb);

    const size_t gs1 = gemm_smem(80, 256, 41);    // ~124 KB
    const size_t gs2 = gemm_smem(128, 128, 73);   // ~141 KB
    const size_t gs3 = gemm_smem(64, 64, 41);     // ~59 KB
    const size_t rs1 = (size_t)(64 * 256 + 2 * 8 * 68) * 4 + 8 * 64 * 16;  // ~78 KB

    cudaFuncSetAttribute((const void*)inproj_gemm<78, 80, 256, 41>,
                         cudaFuncAttributeMaxDynamicSharedMemorySize, (int)gs1);
    cudaFuncSetAttribute((const void*)inproj_gemm<128, 128, 128, 73>,
                         cudaFuncAttributeMaxDynamicSharedMemorySize, (int)gs2);
    cudaFuncSetAttribute((const void*)inproj_gemm<64, 64, 64, 41>,
                         cudaFuncAttributeMaxDynamicSharedMemorySize, (int)gs3);
    cudaFuncSetAttribute((const void*)lstm_rec_l1,
                         cudaFuncAttributeMaxDynamicSharedMemorySize, (int)rs1);

    // ---- Layer 1 ----
    inproj_gemm<78, 80, 256, 41><<<dim3(MX_ / 128, 2), 256, gs1>>>(
        x, w1f_k, w1f_b, w1b_k, w1b_b, xzf, xzb);
    lstm_rec_l1<<<dim3(B_ / 8, 2), 256, rs1>>>(xzf, xzb, w1f_r, w1b_r, b1);

    // ---- Layer 2 ----
    inproj_gemm<128, 128, 128, 73><<<dim3(MX_ / 128, 2), 256, gs2>>>(
        b1, w2f_k, w2f_b, w2b_k, w2b_b, xzf, xzb);
    lstm_rec_l2<<<dim3(B_ / 4, 2), 128>>>(xzf, xzb, w2f_r, w2b_r, b2);

    // ---- Layer 3 ----
    inproj_gemm<64, 64, 64, 41><<<dim3(MX_ / 128, 2), 256, gs3>>>(
        b2, w3f_k, w3f_b, w3b_k, w3b_b, xzf, xzb);
    lstm_rec_l3<<<dim3(B_ / 8, 2), 128>>>(xzf, xzb, w3f_r, w3b_r, b3);

    // ---- Head ----
    head_kernel<<<(B_ + 255) / 256, 256>>>(b3, d3_w, d3_b, cls_w, cls_b, (float*)d_out);
}